// round 2
// baseline (speedup 1.0000x reference)
#include <cuda_runtime.h>
#include <cuda_bf16.h>
#include <cstdint>

// RotationComponent: w_rotated = w @ rot, a_rotated = x @ rot, where rot is a
// normalized randomized Hadamard matrix: rot[i,j] = H[i,j] * rot[0,j] with H
// the 4096x4096 Sylvester Hadamard (symmetric, H[0,:] = +1). Hence
//   (v @ rot)[j] = FWHT(v)[j] * rot[0,j]
// computed exactly from the given rot (scales read from its first row).
//
// One CTA per row. Logical element index i (12 bits) mapping, phase 1:
//   i = c*1024 + tid*4 + e    (c: bits 11,10 | warp: 9..7 | lane: 6..2 | e: 1,0)
//   -> register butterflies on bits {11,10,1,0}, shuffle butterflies on {6..2}
// Transpose through smem, phase 2:
//   i = w_hi*1024 + j*128 + w_lo*64 + lane*2 + e2
//   (w_hi: bits 11,10 | j: 9..7 | w_lo: 6 | lane: 5..1 | e2: 0)
//   -> register butterflies on bits {9,8,7}
// All global traffic vectorized: LDG.128 src, STS.128, LDS.64, LDG.64 rot,
// STG.64 out. Streaming (.cs) hints on the single-pass src/dst traffic.

#define DIM 4096
#define W_ROWS 4096
#define X_ROWS 8192   // 4 * 2048
#define THREADS 256

__global__ __launch_bounds__(THREADS)
void fwht_rotate_kernel(const float* __restrict__ w,
                        const float* __restrict__ x,
                        const float* __restrict__ rot,
                        float* __restrict__ out)
{
    __shared__ float smem[DIM];

    const int row  = blockIdx.x;
    const int tid  = threadIdx.x;
    const int lane = tid & 31;
    const int warp = tid >> 5;

    const float* src = (row < W_ROWS)
        ? (w + (size_t)row * DIM)
        : (x + (size_t)(row - W_ROWS) * DIM);

    // ---- Phase-1 load: v[c*4+e] = src[c*1024 + tid*4 + e] (LDG.128, streaming)
    float v[16];
    #pragma unroll
    for (int c = 0; c < 4; c++) {
        float4 t = __ldcs((const float4*)(src + c * 1024 + tid * 4));
        v[c * 4 + 0] = t.x;
        v[c * 4 + 1] = t.y;
        v[c * 4 + 2] = t.z;
        v[c * 4 + 3] = t.w;
    }

    // ---- Stage A: register butterflies on i-bits {11,10,1,0} (all 4 reg bits)
    #pragma unroll
    for (int m = 8; m >= 1; m >>= 1) {
        #pragma unroll
        for (int r = 0; r < 16; r++) {
            if ((r & m) == 0) {
                float a = v[r];
                float b = v[r | m];
                v[r]     = a + b;
                v[r | m] = a - b;
            }
        }
    }

    // ---- Stage B: shuffle butterflies on i-bits {6..2} (lane bits)
    #pragma unroll
    for (int m = 16; m >= 1; m >>= 1) {
        const bool hi = (lane & m) != 0;
        #pragma unroll
        for (int r = 0; r < 16; r++) {
            float other = __shfl_xor_sync(0xffffffffu, v[r], m);
            v[r] = hi ? (other - v[r]) : (v[r] + other);
        }
    }

    // ---- Transpose write: smem[i] with STS.128 (conflict-free, contiguous)
    #pragma unroll
    for (int c = 0; c < 4; c++) {
        float4 t = make_float4(v[c * 4 + 0], v[c * 4 + 1],
                               v[c * 4 + 2], v[c * 4 + 3]);
        *(float4*)(smem + c * 1024 + tid * 4) = t;
    }
    __syncthreads();

    // ---- Phase-2 read: i = w_hi*1024 + j*128 + w_lo*64 + lane*2 + e2
    //      (LDS.64 x8, conflict-free: 32 lanes cover 256B contiguous)
    const int base = ((warp >> 1) & 3) * 1024 + (warp & 1) * 64 + lane * 2;
    #pragma unroll
    for (int j = 0; j < 8; j++) {
        float2 t = *(const float2*)(smem + base + j * 128);
        v[j * 2 + 0] = t.x;
        v[j * 2 + 1] = t.y;
    }

    // ---- Stage C: register butterflies on i-bits {9,8,7} (j bits 2..0)
    #pragma unroll
    for (int m = 4; m >= 1; m >>= 1) {
        #pragma unroll
        for (int j = 0; j < 8; j++) {
            if ((j & m) == 0) {
                const int p = j | m;
                float a0 = v[j * 2 + 0], b0 = v[p * 2 + 0];
                float a1 = v[j * 2 + 1], b1 = v[p * 2 + 1];
                v[j * 2 + 0] = a0 + b0;
                v[p * 2 + 0] = a0 - b0;
                v[j * 2 + 1] = a1 + b1;
                v[p * 2 + 1] = a1 - b1;
            }
        }
    }

    // ---- Scale by rot[0, i] (LDG.64, L1-hit: row reused by all CTAs) and
    //      store (STG.64 streaming, 256B contiguous per warp instruction)
    float* dst = out + (size_t)row * DIM;
    #pragma unroll
    for (int j = 0; j < 8; j++) {
        const int idx = base + j * 128;
        float2 s = __ldg((const float2*)(rot + idx));
        float2 r;
        r.x = v[j * 2 + 0] * s.x;
        r.y = v[j * 2 + 1] * s.y;
        __stcs((float2*)(dst + idx), r);
    }
}

extern "C" void kernel_launch(void* const* d_in, const int* in_sizes, int n_in,
                              void* d_out, int out_size)
{
    const float* w   = (const float*)d_in[0];   // [4096, 4096]
    const float* x   = (const float*)d_in[1];   // [4, 2048, 4096]
    const float* rot = (const float*)d_in[2];   // [4096, 4096]
    float* out = (float*)d_out;                 // w_rotated then a_rotated

    (void)in_sizes; (void)n_in; (void)out_size;

    fwht_rotate_kernel<<<W_ROWS + X_ROWS, THREADS>>>(w, x, rot, out);
}

// round 3
// speedup vs baseline: 1.3532x; 1.3532x over previous
#include <cuda_runtime.h>
#include <cuda_bf16.h>
#include <cstdint>

// RotationComponent: w_rotated = w @ rot, a_rotated = x @ rot, where rot is a
// normalized randomized Hadamard matrix: rot[i,j] = H[i,j] * s_j / 64, H the
// 4096x4096 Sylvester Hadamard (symmetric, H[0,:] = +1), s_j = +-1. Hence
//   (v @ rot)[j] = FWHT(v)[j] * s_j / 64
// and rot[0,j] = s_j/64 exactly (1/64 = 2^-6 is exact in fp32), so the signs
// are read from rot's first row and packed into 4096 bits by a setup kernel.
//
// Structure identical to the 76us round-1 kernel (scalar, wavefront-optimal
// accesses) except the per-element rot loads are replaced by packed signs.

#define DIM 4096
#define W_ROWS 4096
#define X_ROWS 8192   // 4 * 2048
#define THREADS 256
#define INV_SQRT_N 0.015625f   // 1/64, exact

__device__ unsigned int g_signs[DIM / 32];   // 128 words, 512 B

__global__ void pack_signs_kernel(const float* __restrict__ rot)
{
    const int t = threadIdx.x;           // 0..127, one word per thread
    unsigned int bits = 0;
    #pragma unroll
    for (int b = 0; b < 32; b++) {
        unsigned int s = __float_as_uint(rot[t * 32 + b]) >> 31;  // 1 if negative
        bits |= s << b;
    }
    g_signs[t] = bits;
}

__global__ __launch_bounds__(THREADS)
void fwht_rotate_kernel(const float* __restrict__ w,
                        const float* __restrict__ x,
                        float* __restrict__ out)
{
    __shared__ float smem[DIM];

    const int row  = blockIdx.x;
    const int tid  = threadIdx.x;
    const int lane = tid & 31;
    const int warp = tid >> 5;

    const float* src = (row < W_ROWS)
        ? (w + (size_t)row * DIM)
        : (x + (size_t)(row - W_ROWS) * DIM);

    // ---- Load: v[r] holds element index i = r*256 + tid (coalesced) ----
    float v[16];
    #pragma unroll
    for (int r = 0; r < 16; r++) {
        v[r] = src[r * THREADS + tid];
    }

    // ---- Stage A: butterflies on bits 11..8 (register index r) ----
    #pragma unroll
    for (int m = 8; m >= 1; m >>= 1) {
        #pragma unroll
        for (int r = 0; r < 16; r++) {
            if ((r & m) == 0) {
                float a = v[r];
                float b = v[r | m];
                v[r]     = a + b;
                v[r | m] = a - b;
            }
        }
    }

    // ---- Stage B: butterflies on bits 4..0 (lane index) via shfl_xor ----
    #pragma unroll
    for (int m = 16; m >= 1; m >>= 1) {
        const bool hi = (lane & m) != 0;
        #pragma unroll
        for (int r = 0; r < 16; r++) {
            float other = __shfl_xor_sync(0xffffffffu, v[r], m);
            v[r] = hi ? (other - v[r]) : (v[r] + other);
        }
    }

    // ---- Transpose through smem to expose bits 7..5 as register bits ----
    #pragma unroll
    for (int r = 0; r < 16; r++) {
        smem[r * THREADS + tid] = v[r];
    }
    __syncthreads();

    // Re-read with i' = warp*512 + r2*32 + lane:
    //   lane -> bits 4..0, r2 -> bits 8..5, warp -> bits 11..9.
    const int base_idx = warp * 512 + lane;
    #pragma unroll
    for (int r2 = 0; r2 < 16; r2++) {
        v[r2] = smem[base_idx + r2 * 32];
    }

    // ---- Stage C: butterflies on bits 7..5 (r2 bits 2..0) ----
    #pragma unroll
    for (int m = 4; m >= 1; m >>= 1) {
        #pragma unroll
        for (int r2 = 0; r2 < 16; r2++) {
            if ((r2 & m) == 0) {
                float a = v[r2];
                float b = v[r2 | m];
                v[r2]     = a + b;
                v[r2 | m] = a - b;
            }
        }
    }

    // ---- Sign words for this warp: indices warp*512 + r2*32 + lane
    //      -> word = warp*16 + r2, bit = lane. 16 contiguous words,
    //      loaded as 4 broadcast uint4 (1 sector per wavefront).
    unsigned int sw[16];
    {
        const uint4* sp = (const uint4*)(g_signs + warp * 16);
        #pragma unroll
        for (int q = 0; q < 4; q++) {
            uint4 t = sp[q];
            sw[q * 4 + 0] = t.x;
            sw[q * 4 + 1] = t.y;
            sw[q * 4 + 2] = t.z;
            sw[q * 4 + 3] = t.w;
        }
    }

    // ---- Scale by s_j/64 and store (coalesced 128B per warp instruction) ----
    float* dst = out + (size_t)row * DIM;
    #pragma unroll
    for (int r2 = 0; r2 < 16; r2++) {
        const float c = ((sw[r2] >> lane) & 1u) ? -INV_SQRT_N : INV_SQRT_N;
        dst[base_idx + r2 * 32] = v[r2] * c;
    }
}

extern "C" void kernel_launch(void* const* d_in, const int* in_sizes, int n_in,
                              void* d_out, int out_size)
{
    const float* w   = (const float*)d_in[0];   // [4096, 4096]
    const float* x   = (const float*)d_in[1];   // [4, 2048, 4096]
    const float* rot = (const float*)d_in[2];   // [4096, 4096]
    float* out = (float*)d_out;                 // w_rotated then a_rotated

    (void)in_sizes; (void)n_in; (void)out_size;

    pack_signs_kernel<<<1, DIM / 32>>>(rot);
    fwht_rotate_kernel<<<W_ROWS + X_ROWS, THREADS>>>(w, x, out);
}